// round 2
// baseline (speedup 1.0000x reference)
#include <cuda_runtime.h>

#define NN   20000
#define EE   320000
#define ET   (EE + NN)
#define DD   512
#define HH   4
#define CC   128
#define OUTD 256
#define FIN  127

// ---------------- device scratch (static, no allocation) ----------------
__device__ float  g_xl[NN * DD];     // GAT linear output (per layer, reused)
__device__ float  g_h [NN * DD];     // aggregated output (per layer, reused)
__device__ float  g_hn[NN * DD];     // post-BN layer-1 output (residual source)
__device__ float  g_als[NN * HH];
__device__ float  g_ald[NN * HH];
__device__ float  g_s  [NN * HH];    // softmax denominators
__device__ float  g_eexp[ET * HH];   // per-edge exp(logit)
__device__ int    g_cnt[NN];
__device__ int    g_ptr[NN + 1];
__device__ int    g_cur[NN];
__device__ int    g_csrc[ET];
__device__ int    g_ceid[ET];
__device__ double g_sum[DD];
__device__ double g_sq [DD];
__device__ float  g_scale[DD];
__device__ float  g_shift[DD];

// ---------------- small utility kernels ----------------
__global__ void zero_cnt_k() {
    int i = blockIdx.x * blockDim.x + threadIdx.x;
    if (i < NN) g_cnt[i] = 0;
}
__global__ void zero_s_k() {
    int i = blockIdx.x * blockDim.x + threadIdx.x;
    if (i < NN * HH) g_s[i] = 0.f;
}
__global__ void zero_bn_k() {
    int t = threadIdx.x;
    if (t < DD) { g_sum[t] = 0.0; g_sq[t] = 0.0; }
}

// ---------------- CSR build (edge_index is int32: JAX x64-disabled) -------
__global__ void count_k(const int* __restrict__ ei) {
    int e = blockIdx.x * blockDim.x + threadIdx.x;
    if (e >= ET) return;
    int dst = (e < EE) ? ei[EE + e] : (e - EE);
    atomicAdd(&g_cnt[dst], 1);
}

__global__ void scan_k() {   // one block, 1024 threads; N=20000 -> 20 per thread
    __shared__ int sh[1024];
    int t = threadIdx.x;
    const int CH = 20;
    int base = t * CH;
    int s = 0;
#pragma unroll
    for (int i = 0; i < CH; i++) {
        int idx = base + i;
        if (idx < NN) s += g_cnt[idx];
    }
    sh[t] = s;
    __syncthreads();
    for (int off = 1; off < 1024; off <<= 1) {
        int v = (t >= off) ? sh[t - off] : 0;
        __syncthreads();
        sh[t] += v;
        __syncthreads();
    }
    int run = sh[t] - s;   // exclusive prefix for this chunk
#pragma unroll
    for (int i = 0; i < CH; i++) {
        int idx = base + i;
        if (idx < NN) {
            g_ptr[idx] = run;
            g_cur[idx] = run;
            run += g_cnt[idx];
        }
    }
    if (t == 1023) g_ptr[NN] = sh[1023];
}

__global__ void fill_k(const int* __restrict__ ei) {
    int e = blockIdx.x * blockDim.x + threadIdx.x;
    if (e >= ET) return;
    int src, dst;
    if (e < EE) { src = ei[e]; dst = ei[EE + e]; }
    else        { src = dst = e - EE; }
    int p = atomicAdd(&g_cur[dst], 1);
    g_csrc[p] = src;
    g_ceid[p] = e;
}

// ---------------- GEMM: C[M,N] = A[M,K] @ B[K,N] (+bias) ----------------
// 64x64 tile, 256 threads, 4x4 micro-tile. concat=1 -> A is [X | pos] with
// X having K-1=127 cols.
__global__ void gemm_k(const float* __restrict__ A, const float* __restrict__ posv,
                       int concat,
                       const float* __restrict__ B, const float* __restrict__ bias,
                       float* __restrict__ C, int M, int N, int K)
{
    __shared__ float As[16][65];
    __shared__ float Bs[16][64];
    int tid = threadIdx.x;
    int tx = tid & 15, ty = tid >> 4;
    int bm = blockIdx.y * 64, bn = blockIdx.x * 64;
    float acc[4][4] = {};

    for (int k0 = 0; k0 < K; k0 += 16) {
#pragma unroll
        for (int i = 0; i < 4; i++) {
            int lin = tid + i * 256;
            int m = lin >> 4, kk = lin & 15;
            int row = bm + m, k = k0 + kk;
            float v = 0.f;
            if (row < M)
                v = concat ? (k < K - 1 ? A[row * (K - 1) + k] : posv[row])
                           : A[(long)row * K + k];
            As[kk][m] = v;
        }
#pragma unroll
        for (int i = 0; i < 4; i++) {
            int lin = tid + i * 256;
            int kk = lin >> 6, n = lin & 63;
            Bs[kk][n] = B[(k0 + kk) * N + bn + n];
        }
        __syncthreads();
#pragma unroll
        for (int k = 0; k < 16; k++) {
            float a[4], b[4];
#pragma unroll
            for (int i = 0; i < 4; i++) a[i] = As[k][ty * 4 + i];
#pragma unroll
            for (int j = 0; j < 4; j++) b[j] = Bs[k][tx * 4 + j];
#pragma unroll
            for (int i = 0; i < 4; i++)
#pragma unroll
                for (int j = 0; j < 4; j++) acc[i][j] += a[i] * b[j];
        }
        __syncthreads();
    }
#pragma unroll
    for (int i = 0; i < 4; i++) {
        int row = bm + ty * 4 + i;
        if (row < M) {
#pragma unroll
            for (int j = 0; j < 4; j++) {
                int col = bn + tx * 4 + j;
                C[(long)row * N + col] = acc[i][j] + (bias ? bias[col] : 0.f);
            }
        }
    }
}

// ---------------- per-(node,head) attention dots ----------------
__global__ void al_k(const float* __restrict__ xl,
                     const float* __restrict__ asrc, const float* __restrict__ adst)
{
    int gw = (blockIdx.x * blockDim.x + threadIdx.x) >> 5;
    int lane = threadIdx.x & 31;
    if (gw >= NN * HH) return;
    int n = gw >> 2, h = gw & 3;
    const float* row = xl + (long)n * DD + h * CC;
    float s1 = 0.f, s2 = 0.f;
#pragma unroll
    for (int c = lane; c < CC; c += 32) {
        float v = row[c];
        s1 += v * asrc[h * CC + c];
        s2 += v * adst[h * CC + c];
    }
#pragma unroll
    for (int o = 16; o; o >>= 1) {
        s1 += __shfl_down_sync(0xffffffffu, s1, o);
        s2 += __shfl_down_sync(0xffffffffu, s2, o);
    }
    if (lane == 0) { g_als[n * HH + h] = s1; g_ald[n * HH + h] = s2; }
}

// ---------------- edge pass: exp(leaky(logit)) + denominator ----------------
__global__ void e1_k(const int* __restrict__ ei) {
    int e = blockIdx.x * blockDim.x + threadIdx.x;
    if (e >= ET) return;
    int src, dst;
    if (e < EE) { src = ei[e]; dst = ei[EE + e]; }
    else        { src = dst = e - EE; }
#pragma unroll
    for (int h = 0; h < HH; h++) {
        float v = g_als[src * HH + h] + g_ald[dst * HH + h];
        v = v > 0.f ? v : 0.2f * v;
        float ex = __expf(v);
        g_eexp[e * HH + h] = ex;
        atomicAdd(&g_s[dst * HH + h], ex);
    }
}

// ---------------- aggregation: block per destination node ----------------
__global__ void agg_k(const float* __restrict__ xl, const float* __restrict__ bias,
                      float* __restrict__ out)
{
    int n = blockIdx.x;
    int t = threadIdx.x;      // 128 threads, one channel each, all 4 heads
    int p0 = g_ptr[n], p1 = g_ptr[n + 1];
    float inv0 = 1.f / (g_s[n * 4 + 0] + 1e-16f);
    float inv1 = 1.f / (g_s[n * 4 + 1] + 1e-16f);
    float inv2 = 1.f / (g_s[n * 4 + 2] + 1e-16f);
    float inv3 = 1.f / (g_s[n * 4 + 3] + 1e-16f);
    float a0 = 0.f, a1 = 0.f, a2 = 0.f, a3 = 0.f;
    for (int p = p0; p < p1; p++) {
        int src = g_csrc[p];
        int eid = g_ceid[p];
        float4 ee = *(const float4*)(g_eexp + (long)eid * 4);
        const float* xr = xl + (long)src * DD;
        a0 += ee.x * inv0 * xr[t];
        a1 += ee.y * inv1 * xr[128 + t];
        a2 += ee.z * inv2 * xr[256 + t];
        a3 += ee.w * inv3 * xr[384 + t];
    }
    long base = (long)n * DD;
    out[base + t]       = a0 + bias[t];
    out[base + 128 + t] = a1 + bias[128 + t];
    out[base + 256 + t] = a2 + bias[256 + t];
    out[base + 384 + t] = a3 + bias[384 + t];
}

// ---------------- batch norm ----------------
__global__ void bn_stats_k(const float* __restrict__ h) {
    int t = threadIdx.x;      // 512 threads, one column each
    int r0 = blockIdx.x * 50;
    double s = 0.0, s2 = 0.0;
    for (int i = 0; i < 50; i++) {
        int r = r0 + i;
        if (r < NN) {
            float v = h[(long)r * DD + t];
            s += v;
            s2 += (double)v * (double)v;
        }
    }
    atomicAdd(&g_sum[t], s);
    atomicAdd(&g_sq[t], s2);
}

__global__ void bn_fin_k(const float* __restrict__ g, const float* __restrict__ b) {
    int t = threadIdx.x;
    float mean = (float)(g_sum[t] / (double)NN);
    float var  = (float)(g_sq[t] / (double)NN) - mean * mean;
    float a = g[t] * rsqrtf(var + 1e-5f);
    g_scale[t] = a;
    g_shift[t] = b[t] - mean * a;
}

__global__ void bn_apply_k(const float* __restrict__ in, const float* __restrict__ res,
                           float* __restrict__ out)
{
    int i = blockIdx.x * blockDim.x + threadIdx.x;
    if (i >= NN * DD) return;
    int j = i & (DD - 1);
    float v = in[i] * g_scale[j] + g_shift[j];
    v = v > 0.f ? v : 0.01f * v;
    if (res) v += res[i];
    out[i] = v;
}

// ---------------- launch ----------------
extern "C" void kernel_launch(void* const* d_in, const int* in_sizes, int n_in,
                              void* d_out, int out_size)
{
    const float* X    = (const float*)d_in[0];
    const int*   ei   = (const int*)d_in[1];
    const float* pos  = (const float*)d_in[3];
    const float* W1   = (const float*)d_in[4];
    const float* as1  = (const float*)d_in[5];
    const float* ad1  = (const float*)d_in[6];
    const float* b1   = (const float*)d_in[7];
    const float* W2   = (const float*)d_in[8];
    const float* as2  = (const float*)d_in[9];
    const float* ad2  = (const float*)d_in[10];
    const float* b2   = (const float*)d_in[11];
    const float* bn1g = (const float*)d_in[12];
    const float* bn1b = (const float*)d_in[13];
    const float* bn2g = (const float*)d_in[14];
    const float* bn2b = (const float*)d_in[15];
    const float* outW = (const float*)d_in[18];
    const float* outb = (const float*)d_in[19];
    float*       out  = (float*)d_out;

    float *xl, *h, *hn;
    cudaGetSymbolAddress((void**)&xl, g_xl);
    cudaGetSymbolAddress((void**)&h,  g_h);
    cudaGetSymbolAddress((void**)&hn, g_hn);

    const int EB = (ET + 255) / 256;
    dim3 gGat(DD / 64, (NN + 63) / 64);
    dim3 gOut(OUTD / 64, (NN + 63) / 64);
    int alBlocks = (NN * HH * 32 + 255) / 256;
    int ewBlocks = (NN * DD + 255) / 256;
    int bnBlocks = (NN + 49) / 50;

    // CSR (shared by both layers)
    zero_cnt_k<<<(NN + 255) / 256, 256>>>();
    count_k<<<EB, 256>>>(ei);
    scan_k<<<1, 1024>>>();
    fill_k<<<EB, 256>>>(ei);

    // ---- layer 1 ----
    gemm_k<<<gGat, 256>>>(X, pos, 1, W1, nullptr, xl, NN, DD, FIN + 1);
    al_k<<<alBlocks, 256>>>(xl, as1, ad1);
    zero_s_k<<<(NN * HH + 255) / 256, 256>>>();
    e1_k<<<EB, 256>>>(ei);
    agg_k<<<NN, 128>>>(xl, b1, h);
    zero_bn_k<<<1, 512>>>();
    bn_stats_k<<<bnBlocks, 512>>>(h);
    bn_fin_k<<<1, 512>>>(bn1g, bn1b);
    bn_apply_k<<<ewBlocks, 256>>>(h, nullptr, hn);

    // ---- layer 2 ----
    gemm_k<<<gGat, 256>>>(hn, nullptr, 0, W2, nullptr, xl, NN, DD, DD);
    al_k<<<alBlocks, 256>>>(xl, as2, ad2);
    zero_s_k<<<(NN * HH + 255) / 256, 256>>>();
    e1_k<<<EB, 256>>>(ei);
    agg_k<<<NN, 128>>>(xl, b2, h);
    zero_bn_k<<<1, 512>>>();
    bn_stats_k<<<bnBlocks, 512>>>(h);
    bn_fin_k<<<1, 512>>>(bn2g, bn2b);
    bn_apply_k<<<ewBlocks, 256>>>(h, hn, h);   // in-place + residual

    // ---- output projection ----
    gemm_k<<<gOut, 256>>>(h, nullptr, 0, outW, outb, out, NN, OUTD, DD);
}

// round 3
// speedup vs baseline: 1.1077x; 1.1077x over previous
#include <cuda_runtime.h>

#define NN   20000
#define EE   320000
#define ET   (EE + NN)
#define DD   512
#define HH   4
#define CC   128
#define OUTD 256
#define FIN  127

// ---------------- device scratch (static, no allocation) ----------------
__device__ float  g_xp[NN * 128];    // packed [X | pos], K=128 aligned
__device__ float  g_xl[NN * DD];     // GAT linear output (per layer, reused)
__device__ float  g_h [NN * DD];     // aggregated output (per layer, reused)
__device__ float  g_hn[NN * DD];     // post-BN layer-1 output (residual source)
__device__ float  g_als[NN * HH];
__device__ float  g_ald[NN * HH];
__device__ float  g_eexp[ET * HH];   // per-edge exp(logit)
__device__ int    g_cnt[NN];
__device__ int    g_ptr[NN + 1];
__device__ int    g_cur[NN];
__device__ int    g_csrc[ET];
__device__ int    g_ceid[ET];
__device__ double g_sum[DD];
__device__ double g_sq [DD];
__device__ float  g_scale[DD];
__device__ float  g_shift[DD];

// ---------------- small utility kernels ----------------
__global__ void zero_cnt_k() {
    int i = blockIdx.x * blockDim.x + threadIdx.x;
    if (i < NN) g_cnt[i] = 0;
}
__global__ void zero_bn_k() {
    int t = threadIdx.x;
    if (t < DD) { g_sum[t] = 0.0; g_sq[t] = 0.0; }
}
__global__ void pack_k(const float* __restrict__ X, const float* __restrict__ pos) {
    int i = blockIdx.x * blockDim.x + threadIdx.x;
    if (i >= NN * 128) return;
    int r = i >> 7, c = i & 127;
    g_xp[i] = (c < FIN) ? X[r * FIN + c] : pos[r];
}

// ---------------- CSR build (edge_index is int32) ----------------
__global__ void count_k(const int* __restrict__ ei) {
    int e = blockIdx.x * blockDim.x + threadIdx.x;
    if (e >= ET) return;
    int dst = (e < EE) ? ei[EE + e] : (e - EE);
    atomicAdd(&g_cnt[dst], 1);
}

__global__ void scan_k() {   // one block, 1024 threads; N=20000 -> 20 per thread
    __shared__ int sh[1024];
    int t = threadIdx.x;
    const int CH = 20;
    int base = t * CH;
    int s = 0;
#pragma unroll
    for (int i = 0; i < CH; i++) {
        int idx = base + i;
        if (idx < NN) s += g_cnt[idx];
    }
    sh[t] = s;
    __syncthreads();
    for (int off = 1; off < 1024; off <<= 1) {
        int v = (t >= off) ? sh[t - off] : 0;
        __syncthreads();
        sh[t] += v;
        __syncthreads();
    }
    int run = sh[t] - s;
#pragma unroll
    for (int i = 0; i < CH; i++) {
        int idx = base + i;
        if (idx < NN) {
            g_ptr[idx] = run;
            g_cur[idx] = run;
            run += g_cnt[idx];
        }
    }
    if (t == 1023) g_ptr[NN] = sh[1023];
}

__global__ void fill_k(const int* __restrict__ ei) {
    int e = blockIdx.x * blockDim.x + threadIdx.x;
    if (e >= ET) return;
    int src, dst;
    if (e < EE) { src = ei[e]; dst = ei[EE + e]; }
    else        { src = dst = e - EE; }
    int p = atomicAdd(&g_cur[dst], 1);
    g_csrc[p] = src;
    g_ceid[p] = e;
}

// ---------------- GEMM: C[M,N] = A[M,K] @ B[K,N] (+opt bias) --------------
// 128x128 tile, 256 threads, 8x8 micro-tile, double-buffered smem, float4.
// Requires K % 8 == 0, N % 128 == 0, A rows 16B aligned (K % 4 == 0).
__global__ void __launch_bounds__(256) gemm128_k(
    const float* __restrict__ A, const float* __restrict__ B,
    const float* __restrict__ bias, float* __restrict__ C,
    int M, int N, int K)
{
    __shared__ float As[2][8][128];
    __shared__ float Bs[2][8][128];
    int tid = threadIdx.x;
    int tx = tid & 15, ty = tid >> 4;
    int bm = blockIdx.y * 128, bn = blockIdx.x * 128;

    int arow = tid >> 1, acol = (tid & 1) * 4;
    int brow = tid >> 5, bcol = (tid & 31) * 4;
    bool aval = (bm + arow) < M;
    const float* Aptr = A + (long)(bm + arow) * K + acol;
    const float* Bptr = B + (long)brow * N + bn + bcol;

    float4 a4 = aval ? *(const float4*)Aptr : make_float4(0.f, 0.f, 0.f, 0.f);
    float4 b4 = *(const float4*)Bptr;

    float acc[8][8] = {};
    int buf = 0;
    As[0][acol + 0][arow] = a4.x;
    As[0][acol + 1][arow] = a4.y;
    As[0][acol + 2][arow] = a4.z;
    As[0][acol + 3][arow] = a4.w;
    *(float4*)&Bs[0][brow][bcol] = b4;
    __syncthreads();

    for (int k0 = 8; k0 <= K; k0 += 8) {
        bool has = k0 < K;
        if (has) {
            a4 = aval ? *(const float4*)(Aptr + k0) : make_float4(0.f, 0.f, 0.f, 0.f);
            b4 = *(const float4*)(Bptr + (long)k0 * N);
        }
#pragma unroll
        for (int kk = 0; kk < 8; kk++) {
            float4 a0 = *(const float4*)&As[buf][kk][ty * 8];
            float4 a1 = *(const float4*)&As[buf][kk][ty * 8 + 4];
            float4 b0 = *(const float4*)&Bs[buf][kk][tx * 8];
            float4 b1 = *(const float4*)&Bs[buf][kk][tx * 8 + 4];
            float av[8] = {a0.x, a0.y, a0.z, a0.w, a1.x, a1.y, a1.z, a1.w};
            float bv[8] = {b0.x, b0.y, b0.z, b0.w, b1.x, b1.y, b1.z, b1.w};
#pragma unroll
            for (int i = 0; i < 8; i++)
#pragma unroll
                for (int j = 0; j < 8; j++) acc[i][j] += av[i] * bv[j];
        }
        if (has) {
            buf ^= 1;
            As[buf][acol + 0][arow] = a4.x;
            As[buf][acol + 1][arow] = a4.y;
            As[buf][acol + 2][arow] = a4.z;
            As[buf][acol + 3][arow] = a4.w;
            *(float4*)&Bs[buf][brow][bcol] = b4;
            __syncthreads();
        }
    }

#pragma unroll
    for (int i = 0; i < 8; i++) {
        int row = bm + ty * 8 + i;
        if (row < M) {
#pragma unroll
            for (int j = 0; j < 8; j += 4) {
                int col = bn + tx * 8 + j;
                float4 v;
                v.x = acc[i][j + 0] + (bias ? bias[col + 0] : 0.f);
                v.y = acc[i][j + 1] + (bias ? bias[col + 1] : 0.f);
                v.z = acc[i][j + 2] + (bias ? bias[col + 2] : 0.f);
                v.w = acc[i][j + 3] + (bias ? bias[col + 3] : 0.f);
                *(float4*)&C[(long)row * N + col] = v;
            }
        }
    }
}

// ---------------- per-(node,head) attention dots ----------------
__global__ void al_k(const float* __restrict__ xl,
                     const float* __restrict__ asrc, const float* __restrict__ adst)
{
    int gw = (blockIdx.x * blockDim.x + threadIdx.x) >> 5;
    int lane = threadIdx.x & 31;
    if (gw >= NN * HH) return;
    int n = gw >> 2, h = gw & 3;
    const float* row = xl + (long)n * DD + h * CC;
    float s1 = 0.f, s2 = 0.f;
#pragma unroll
    for (int c = lane; c < CC; c += 32) {
        float v = row[c];
        s1 += v * asrc[h * CC + c];
        s2 += v * adst[h * CC + c];
    }
#pragma unroll
    for (int o = 16; o; o >>= 1) {
        s1 += __shfl_down_sync(0xffffffffu, s1, o);
        s2 += __shfl_down_sync(0xffffffffu, s2, o);
    }
    if (lane == 0) { g_als[n * HH + h] = s1; g_ald[n * HH + h] = s2; }
}

// ---------------- edge pass: exp(leaky(logit)) (no atomics) ---------------
__global__ void e1_k(const int* __restrict__ ei) {
    int e = blockIdx.x * blockDim.x + threadIdx.x;
    if (e >= ET) return;
    int src, dst;
    if (e < EE) { src = ei[e]; dst = ei[EE + e]; }
    else        { src = dst = e - EE; }
    float4 as_ = *(const float4*)(g_als + (long)src * 4);
    float4 ad_ = *(const float4*)(g_ald + (long)dst * 4);
    float4 r;
    float v;
    v = as_.x + ad_.x; v = v > 0.f ? v : 0.2f * v; r.x = __expf(v);
    v = as_.y + ad_.y; v = v > 0.f ? v : 0.2f * v; r.y = __expf(v);
    v = as_.z + ad_.z; v = v > 0.f ? v : 0.2f * v; r.z = __expf(v);
    v = as_.w + ad_.w; v = v > 0.f ? v : 0.2f * v; r.w = __expf(v);
    *(float4*)(g_eexp + (long)e * 4) = r;
}

// ---------------- aggregation: block per destination node ----------------
// Also computes softmax denominators in-loop (sum of exp over incident edges).
__global__ void agg_k(const float* __restrict__ xl, const float* __restrict__ bias,
                      float* __restrict__ out)
{
    int n = blockIdx.x;
    int t = threadIdx.x;      // 128 threads, one channel each, all 4 heads
    int p0 = g_ptr[n], p1 = g_ptr[n + 1];
    float a0 = 0.f, a1 = 0.f, a2 = 0.f, a3 = 0.f;
    float s0 = 0.f, s1 = 0.f, s2 = 0.f, s3 = 0.f;
    for (int p = p0; p < p1; p++) {
        int src = g_csrc[p];
        int eid = g_ceid[p];
        float4 ee = *(const float4*)(g_eexp + (long)eid * 4);
        const float* xr = xl + (long)src * DD;
        s0 += ee.x; s1 += ee.y; s2 += ee.z; s3 += ee.w;
        a0 += ee.x * xr[t];
        a1 += ee.y * xr[128 + t];
        a2 += ee.z * xr[256 + t];
        a3 += ee.w * xr[384 + t];
    }
    long base = (long)n * DD;
    out[base + t]       = a0 / (s0 + 1e-16f) + bias[t];
    out[base + 128 + t] = a1 / (s1 + 1e-16f) + bias[128 + t];
    out[base + 256 + t] = a2 / (s2 + 1e-16f) + bias[256 + t];
    out[base + 384 + t] = a3 / (s3 + 1e-16f) + bias[384 + t];
}

// ---------------- batch norm ----------------
__global__ void bn_stats_k(const float* __restrict__ h) {
    int t = threadIdx.x;      // 512 threads, one column each
    int r0 = blockIdx.x * 50;
    double s = 0.0, s2 = 0.0;
    for (int i = 0; i < 50; i++) {
        int r = r0 + i;
        if (r < NN) {
            float v = h[(long)r * DD + t];
            s += v;
            s2 += (double)v * (double)v;
        }
    }
    atomicAdd(&g_sum[t], s);
    atomicAdd(&g_sq[t], s2);
}

__global__ void bn_fin_k(const float* __restrict__ g, const float* __restrict__ b) {
    int t = threadIdx.x;
    float mean = (float)(g_sum[t] / (double)NN);
    float var  = (float)(g_sq[t] / (double)NN) - mean * mean;
    float a = g[t] * rsqrtf(var + 1e-5f);
    g_scale[t] = a;
    g_shift[t] = b[t] - mean * a;
}

__global__ void bn_apply_k(const float* __restrict__ in, const float* __restrict__ res,
                           float* __restrict__ out)
{
    int i = blockIdx.x * blockDim.x + threadIdx.x;
    if (i >= NN * DD) return;
    int j = i & (DD - 1);
    float v = in[i] * g_scale[j] + g_shift[j];
    v = v > 0.f ? v : 0.01f * v;
    if (res) v += res[i];
    out[i] = v;
}

// ---------------- launch ----------------
extern "C" void kernel_launch(void* const* d_in, const int* in_sizes, int n_in,
                              void* d_out, int out_size)
{
    const float* X    = (const float*)d_in[0];
    const int*   ei   = (const int*)d_in[1];
    const float* pos  = (const float*)d_in[3];
    const float* W1   = (const float*)d_in[4];
    const float* as1  = (const float*)d_in[5];
    const float* ad1  = (const float*)d_in[6];
    const float* b1   = (const float*)d_in[7];
    const float* W2   = (const float*)d_in[8];
    const float* as2  = (const float*)d_in[9];
    const float* ad2  = (const float*)d_in[10];
    const float* b2   = (const float*)d_in[11];
    const float* bn1g = (const float*)d_in[12];
    const float* bn1b = (const float*)d_in[13];
    const float* bn2g = (const float*)d_in[14];
    const float* bn2b = (const float*)d_in[15];
    const float* outW = (const float*)d_in[18];
    const float* outb = (const float*)d_in[19];
    float*       out  = (float*)d_out;

    float *xp, *xl, *h, *hn;
    cudaGetSymbolAddress((void**)&xp, g_xp);
    cudaGetSymbolAddress((void**)&xl, g_xl);
    cudaGetSymbolAddress((void**)&h,  g_h);
    cudaGetSymbolAddress((void**)&hn, g_hn);

    const int EB = (ET + 255) / 256;
    dim3 gGat(DD / 128, (NN + 127) / 128);
    dim3 gOut(OUTD / 128, (NN + 127) / 128);
    int alBlocks = (NN * HH * 32 + 255) / 256;
    int ewBlocks = (NN * DD + 255) / 256;
    int bnBlocks = (NN + 49) / 50;

    // CSR (shared by both layers) + input packing
    zero_cnt_k<<<(NN + 255) / 256, 256>>>();
    count_k<<<EB, 256>>>(ei);
    scan_k<<<1, 1024>>>();
    fill_k<<<EB, 256>>>(ei);
    pack_k<<<(NN * 128 + 255) / 256, 256>>>(X, pos);

    // ---- layer 1 ----
    gemm128_k<<<gGat, 256>>>(xp, W1, nullptr, xl, NN, DD, FIN + 1);
    al_k<<<alBlocks, 256>>>(xl, as1, ad1);
    e1_k<<<EB, 256>>>(ei);
    agg_k<<<NN, 128>>>(xl, b1, h);
    zero_bn_k<<<1, 512>>>();
    bn_stats_k<<<bnBlocks, 512>>>(h);
    bn_fin_k<<<1, 512>>>(bn1g, bn1b);
    bn_apply_k<<<ewBlocks, 256>>>(h, nullptr, hn);

    // ---- layer 2 ----
    gemm128_k<<<gGat, 256>>>(hn, W2, nullptr, xl, NN, DD, DD);
    al_k<<<alBlocks, 256>>>(xl, as2, ad2);
    e1_k<<<EB, 256>>>(ei);
    agg_k<<<NN, 128>>>(xl, b2, h);
    zero_bn_k<<<1, 512>>>();
    bn_stats_k<<<bnBlocks, 512>>>(h);
    bn_fin_k<<<1, 512>>>(bn2g, bn2b);
    bn_apply_k<<<ewBlocks, 256>>>(h, hn, h);   // in-place + residual

    // ---- output projection ----
    gemm128_k<<<gOut, 256>>>(h, outW, outb, out, NN, OUTD, DD);
}

// round 4
// speedup vs baseline: 1.3016x; 1.1751x over previous
#include <cuda_runtime.h>
#include <mma.h>
using namespace nvcuda;

#define NN   20000
#define EE   320000
#define ET   (EE + NN)
#define DD   512
#define HH   4
#define CC   128
#define OUTD 256
#define FIN  127

// ---------------- device scratch (static, no allocation) ----------------
__device__ float  g_xp[NN * 128];    // packed [X | pos], K=128 aligned
__device__ float  g_xl[NN * DD];
__device__ float  g_h [NN * DD];
__device__ float  g_hn[NN * DD];
__device__ float  g_als[NN * HH];
__device__ float  g_ald[NN * HH];
__device__ float  g_eexp[ET * HH];
__device__ int    g_cnt[NN];
__device__ int    g_ptr[NN + 1];
__device__ int    g_cur[NN];
__device__ int    g_csrc[ET];
__device__ int    g_ceid[ET];
__device__ double g_sum[DD];
__device__ double g_sq [DD];
__device__ float  g_scale[DD];
__device__ float  g_shift[DD];

// ---------------- small utility kernels ----------------
__global__ void zero_cnt_k() {
    int i = blockIdx.x * blockDim.x + threadIdx.x;
    if (i < NN) g_cnt[i] = 0;
}
__global__ void zero_bn_k() {
    int t = threadIdx.x;
    if (t < DD) { g_sum[t] = 0.0; g_sq[t] = 0.0; }
}
__global__ void pack_k(const float* __restrict__ X, const float* __restrict__ pos) {
    int i = blockIdx.x * blockDim.x + threadIdx.x;
    if (i >= NN * 128) return;
    int r = i >> 7, c = i & 127;
    g_xp[i] = (c < FIN) ? X[r * FIN + c] : pos[r];
}

// ---------------- CSR build (edge_index is int32) ----------------
__global__ void count_k(const int* __restrict__ ei) {
    int e = blockIdx.x * blockDim.x + threadIdx.x;
    if (e >= ET) return;
    int dst = (e < EE) ? ei[EE + e] : (e - EE);
    atomicAdd(&g_cnt[dst], 1);
}

__global__ void scan_k() {
    __shared__ int sh[1024];
    int t = threadIdx.x;
    const int CH = 20;
    int base = t * CH;
    int s = 0;
#pragma unroll
    for (int i = 0; i < CH; i++) {
        int idx = base + i;
        if (idx < NN) s += g_cnt[idx];
    }
    sh[t] = s;
    __syncthreads();
    for (int off = 1; off < 1024; off <<= 1) {
        int v = (t >= off) ? sh[t - off] : 0;
        __syncthreads();
        sh[t] += v;
        __syncthreads();
    }
    int run = sh[t] - s;
#pragma unroll
    for (int i = 0; i < CH; i++) {
        int idx = base + i;
        if (idx < NN) {
            g_ptr[idx] = run;
            g_cur[idx] = run;
            run += g_cnt[idx];
        }
    }
    if (t == 1023) g_ptr[NN] = sh[1023];
}

__global__ void fill_k(const int* __restrict__ ei) {
    int e = blockIdx.x * blockDim.x + threadIdx.x;
    if (e >= ET) return;
    int src, dst;
    if (e < EE) { src = ei[e]; dst = ei[EE + e]; }
    else        { src = dst = e - EE; }
    int p = atomicAdd(&g_cur[dst], 1);
    g_csrc[p] = src;
    g_ceid[p] = e;
}

// ---------------- tensor-core GEMM (tf32 wmma) ----------------
// C[M,N] = A[M,K] @ B[K,N] (+opt bias). 128x128 block tile, KC=32 chunks,
// 8 warps, warp tile 64x32 (4x2 wmma m16n16k8 fragments).
// Requires: K % 32 == 0, N % 128 == 0, all pointers 16B-aligned.
#define KC 32
__global__ void __launch_bounds__(256) gemm_tc_k(
    const float* __restrict__ A, const float* __restrict__ B,
    const float* __restrict__ bias, float* __restrict__ C,
    int M, int N, int K)
{
    __shared__ float As[128][40];   // 20.5 KB, ld=40
    __shared__ float Bs[KC][132];   // 16.9 KB, ld=132

    int tid = threadIdx.x;
    int warp = tid >> 5, lane = tid & 31;
    int wm = (warp & 1) * 64;       // warp row offset in tile
    int wn = (warp >> 1) * 32;      // warp col offset in tile
    int bm = blockIdx.y * 128, bn = blockIdx.x * 128;

    wmma::fragment<wmma::accumulator, 16, 16, 8, float> c[4][2];
#pragma unroll
    for (int mi = 0; mi < 4; mi++)
#pragma unroll
        for (int ni = 0; ni < 2; ni++)
            wmma::fill_fragment(c[mi][ni], 0.f);

    // A-load mapping: 128 rows x 8 float4 per row; thread t iter i -> idx
    int a_row = (tid >> 3);          // base row for iter 0 (stride 32 rows/iter)
    int a_c4  = (tid & 7) * 4;
    // B-load mapping: 32 rows x 32 float4 per row
    int b_kr  = (tid >> 5);          // base k-row (stride 8/iter)
    int b_c4  = (tid & 31) * 4;

    float4 ar[4], br[4];
    // prefetch chunk 0
#pragma unroll
    for (int i = 0; i < 4; i++) {
        int gr = bm + a_row + i * 32;
        ar[i] = (gr < M) ? *(const float4*)&A[(long)gr * K + a_c4]
                         : make_float4(0.f, 0.f, 0.f, 0.f);
        br[i] = *(const float4*)&B[(long)(b_kr + i * 8) * N + bn + b_c4];
    }

    int nChunks = K / KC;
    for (int ch = 0; ch < nChunks; ch++) {
        // regs -> smem (with tf32 rounding)
#pragma unroll
        for (int i = 0; i < 4; i++) {
            int r = a_row + i * 32;
            As[r][a_c4 + 0] = wmma::__float_to_tf32(ar[i].x);
            As[r][a_c4 + 1] = wmma::__float_to_tf32(ar[i].y);
            As[r][a_c4 + 2] = wmma::__float_to_tf32(ar[i].z);
            As[r][a_c4 + 3] = wmma::__float_to_tf32(ar[i].w);
            int kr = b_kr + i * 8;
            Bs[kr][b_c4 + 0] = wmma::__float_to_tf32(br[i].x);
            Bs[kr][b_c4 + 1] = wmma::__float_to_tf32(br[i].y);
            Bs[kr][b_c4 + 2] = wmma::__float_to_tf32(br[i].z);
            Bs[kr][b_c4 + 3] = wmma::__float_to_tf32(br[i].w);
        }
        __syncthreads();

        // prefetch next chunk
        if (ch + 1 < nChunks) {
            int k0 = (ch + 1) * KC;
#pragma unroll
            for (int i = 0; i < 4; i++) {
                int gr = bm + a_row + i * 32;
                ar[i] = (gr < M) ? *(const float4*)&A[(long)gr * K + k0 + a_c4]
                                 : make_float4(0.f, 0.f, 0.f, 0.f);
                br[i] = *(const float4*)&B[(long)(k0 + b_kr + i * 8) * N + bn + b_c4];
            }
        }

#pragma unroll
        for (int ks = 0; ks < KC / 8; ks++) {
            wmma::fragment<wmma::matrix_a, 16, 16, 8, wmma::precision::tf32, wmma::row_major> a[4];
            wmma::fragment<wmma::matrix_b, 16, 16, 8, wmma::precision::tf32, wmma::row_major> b[2];
#pragma unroll
            for (int mi = 0; mi < 4; mi++)
                wmma::load_matrix_sync(a[mi], &As[wm + mi * 16][ks * 8], 40);
#pragma unroll
            for (int ni = 0; ni < 2; ni++)
                wmma::load_matrix_sync(b[ni], &Bs[ks * 8][wn + ni * 16], 132);
#pragma unroll
            for (int mi = 0; mi < 4; mi++)
#pragma unroll
                for (int ni = 0; ni < 2; ni++)
                    wmma::mma_sync(c[mi][ni], a[mi], b[ni], c[mi][ni]);
        }
        __syncthreads();
    }

    // epilogue: bounce each 16x16 fragment through smem (reuse As), guarded rows
    float* bounce = &As[0][0] + warp * 320;   // 16x20 per warp
    int er = lane >> 1;
    int ec = (lane & 1) * 8;
#pragma unroll
    for (int mi = 0; mi < 4; mi++) {
#pragma unroll
        for (int ni = 0; ni < 2; ni++) {
            wmma::store_matrix_sync(bounce, c[mi][ni], 20, wmma::mem_row_major);
            __syncwarp();
            int grow = bm + wm + mi * 16 + er;
            if (grow < M) {
                int gcol = bn + wn + ni * 16 + ec;
                float* dst = &C[(long)grow * N + gcol];
                const float* srcb = &bounce[er * 20 + ec];
                if (bias) {
#pragma unroll
                    for (int j = 0; j < 8; j++) dst[j] = srcb[j] + bias[gcol + j];
                } else {
                    float4 v0 = *(const float4*)&srcb[0];
                    float4 v1 = *(const float4*)&srcb[4];
                    *(float4*)&dst[0] = v0;
                    *(float4*)&dst[4] = v1;
                }
            }
            __syncwarp();
        }
    }
}

// ---------------- per-(node,head) attention dots ----------------
__global__ void al_k(const float* __restrict__ xl,
                     const float* __restrict__ asrc, const float* __restrict__ adst)
{
    int gw = (blockIdx.x * blockDim.x + threadIdx.x) >> 5;
    int lane = threadIdx.x & 31;
    if (gw >= NN * HH) return;
    int n = gw >> 2, h = gw & 3;
    const float* row = xl + (long)n * DD + h * CC;
    float s1 = 0.f, s2 = 0.f;
#pragma unroll
    for (int c = lane; c < CC; c += 32) {
        float v = row[c];
        s1 += v * asrc[h * CC + c];
        s2 += v * adst[h * CC + c];
    }
#pragma unroll
    for (int o = 16; o; o >>= 1) {
        s1 += __shfl_down_sync(0xffffffffu, s1, o);
        s2 += __shfl_down_sync(0xffffffffu, s2, o);
    }
    if (lane == 0) { g_als[n * HH + h] = s1; g_ald[n * HH + h] = s2; }
}

// ---------------- edge pass: exp(leaky(logit)) ----------------
__global__ void e1_k(const int* __restrict__ ei) {
    int e = blockIdx.x * blockDim.x + threadIdx.x;
    if (e >= ET) return;
    int src, dst;
    if (e < EE) { src = ei[e]; dst = ei[EE + e]; }
    else        { src = dst = e - EE; }
    float4 as_ = *(const float4*)(g_als + (long)src * 4);
    float4 ad_ = *(const float4*)(g_ald + (long)dst * 4);
    float4 r;
    float v;
    v = as_.x + ad_.x; v = v > 0.f ? v : 0.2f * v; r.x = __expf(v);
    v = as_.y + ad_.y; v = v > 0.f ? v : 0.2f * v; r.y = __expf(v);
    v = as_.z + ad_.z; v = v > 0.f ? v : 0.2f * v; r.z = __expf(v);
    v = as_.w + ad_.w; v = v > 0.f ? v : 0.2f * v; r.w = __expf(v);
    *(float4*)(g_eexp + (long)e * 4) = r;
}

// ---------------- aggregation: block per destination node ----------------
__global__ void agg_k(const float* __restrict__ xl, const float* __restrict__ bias,
                      float* __restrict__ out)
{
    int n = blockIdx.x;
    int t = threadIdx.x;
    int p0 = g_ptr[n], p1 = g_ptr[n + 1];
    float a0 = 0.f, a1 = 0.f, a2 = 0.f, a3 = 0.f;
    float s0 = 0.f, s1 = 0.f, s2 = 0.f, s3 = 0.f;
    for (int p = p0; p < p1; p++) {
        int src = g_csrc[p];
        int eid = g_ceid[p];
        float4 ee = *(const float4*)(g_eexp + (long)eid * 4);
        const float* xr = xl + (long)src * DD;
        s0 += ee.x; s1 += ee.y; s2 += ee.z; s3 += ee.w;
        a0 += ee.x * xr[t];
        a1 += ee.y * xr[128 + t];
        a2 += ee.z * xr[256 + t];
        a3 += ee.w * xr[384 + t];
    }
    long base = (long)n * DD;
    out[base + t]       = a0 / (s0 + 1e-16f) + bias[t];
    out[base + 128 + t] = a1 / (s1 + 1e-16f) + bias[128 + t];
    out[base + 256 + t] = a2 / (s2 + 1e-16f) + bias[256 + t];
    out[base + 384 + t] = a3 / (s3 + 1e-16f) + bias[384 + t];
}

// ---------------- batch norm ----------------
__global__ void bn_stats_k(const float* __restrict__ h) {
    int t = threadIdx.x;
    int r0 = blockIdx.x * 50;
    double s = 0.0, s2 = 0.0;
    for (int i = 0; i < 50; i++) {
        int r = r0 + i;
        if (r < NN) {
            float v = h[(long)r * DD + t];
            s += v;
            s2 += (double)v * (double)v;
        }
    }
    atomicAdd(&g_sum[t], s);
    atomicAdd(&g_sq[t], s2);
}

__global__ void bn_fin_k(const float* __restrict__ g, const float* __restrict__ b) {
    int t = threadIdx.x;
    float mean = (float)(g_sum[t] / (double)NN);
    float var  = (float)(g_sq[t] / (double)NN) - mean * mean;
    float a = g[t] * rsqrtf(var + 1e-5f);
    g_scale[t] = a;
    g_shift[t] = b[t] - mean * a;
}

__global__ void bn_apply_k(const float* __restrict__ in, const float* __restrict__ res,
                           float* __restrict__ out)
{
    int i = blockIdx.x * blockDim.x + threadIdx.x;
    if (i >= NN * DD) return;
    int j = i & (DD - 1);
    float v = in[i] * g_scale[j] + g_shift[j];
    v = v > 0.f ? v : 0.01f * v;
    if (res) v += res[i];
    out[i] = v;
}

// ---------------- launch ----------------
extern "C" void kernel_launch(void* const* d_in, const int* in_sizes, int n_in,
                              void* d_out, int out_size)
{
    const float* X    = (const float*)d_in[0];
    const int*   ei   = (const int*)d_in[1];
    const float* pos  = (const float*)d_in[3];
    const float* W1   = (const float*)d_in[4];
    const float* as1  = (const float*)d_in[5];
    const float* ad1  = (const float*)d_in[6];
    const float* b1   = (const float*)d_in[7];
    const float* W2   = (const float*)d_in[8];
    const float* as2  = (const float*)d_in[9];
    const float* ad2  = (const float*)d_in[10];
    const float* b2   = (const float*)d_in[11];
    const float* bn1g = (const float*)d_in[12];
    const float* bn1b = (const float*)d_in[13];
    const float* bn2g = (const float*)d_in[14];
    const float* bn2b = (const float*)d_in[15];
    const float* outW = (const float*)d_in[18];
    const float* outb = (const float*)d_in[19];
    float*       out  = (float*)d_out;

    float *xp, *xl, *h, *hn;
    cudaGetSymbolAddress((void**)&xp, g_xp);
    cudaGetSymbolAddress((void**)&xl, g_xl);
    cudaGetSymbolAddress((void**)&h,  g_h);
    cudaGetSymbolAddress((void**)&hn, g_hn);

    const int EB = (ET + 255) / 256;
    dim3 gGat(DD / 128, (NN + 127) / 128);
    dim3 gOut(OUTD / 128, (NN + 127) / 128);
    int alBlocks = (NN * HH * 32 + 255) / 256;
    int ewBlocks = (NN * DD + 255) / 256;
    int bnBlocks = (NN + 49) / 50;

    zero_cnt_k<<<(NN + 255) / 256, 256>>>();
    count_k<<<EB, 256>>>(ei);
    scan_k<<<1, 1024>>>();
    fill_k<<<EB, 256>>>(ei);
    pack_k<<<(NN * 128 + 255) / 256, 256>>>(X, pos);

    // ---- layer 1 ----
    gemm_tc_k<<<gGat, 256>>>(xp, W1, nullptr, xl, NN, DD, FIN + 1);
    al_k<<<alBlocks, 256>>>(xl, as1, ad1);
    e1_k<<<EB, 256>>>(ei);
    agg_k<<<NN, 128>>>(xl, b1, h);
    zero_bn_k<<<1, 512>>>();
    bn_stats_k<<<bnBlocks, 512>>>(h);
    bn_fin_k<<<1, 512>>>(bn1g, bn1b);
    bn_apply_k<<<ewBlocks, 256>>>(h, nullptr, hn);

    // ---- layer 2 ----
    gemm_tc_k<<<gGat, 256>>>(hn, W2, nullptr, xl, NN, DD, DD);
    al_k<<<alBlocks, 256>>>(xl, as2, ad2);
    e1_k<<<EB, 256>>>(ei);
    agg_k<<<NN, 128>>>(xl, b2, h);
    zero_bn_k<<<1, 512>>>();
    bn_stats_k<<<bnBlocks, 512>>>(h);
    bn_fin_k<<<1, 512>>>(bn2g, bn2b);
    bn_apply_k<<<ewBlocks, 256>>>(h, hn, h);

    // ---- output projection ----
    gemm_tc_k<<<gOut, 256>>>(h, outW, outb, out, NN, OUTD, DD);
}